// round 1
// baseline (speedup 1.0000x reference)
#include <cuda_runtime.h>
#include <cuda_bf16.h>

// Problem dims (fixed by reference)
#define B_DIM   64
#define OUT_DIM 512
#define M_DIM   5
#define IN_DIM  1024

// Scratch (device globals; no allocation in kernel_launch)
__device__ float g_xT[IN_DIM * B_DIM];     // transposed x: xT[i][b]
__device__ float g_half[IN_DIM];           // 0.5 * Dendritic_W2
__device__ float g_sg_total;               // sum_i 0.5*D2[i]

__device__ __forceinline__ float tanh_apx(float v) {
    float r;
    asm("tanh.approx.f32 %0, %1;" : "=f"(r) : "f"(v));
    return r;
}

// ---------------------------------------------------------------------------
// Kernel A: g_half[i] = 0.5*D2[i]; g_sg_total = sum(g_half)
// single block, 1024 threads
// ---------------------------------------------------------------------------
__global__ void prep_kernel(const float* __restrict__ D2) {
    int i = threadIdx.x;
    float v = 0.5f * D2[i];
    g_half[i] = v;

    // block reduce
    __shared__ float warp_sums[32];
    float s = v;
    #pragma unroll
    for (int off = 16; off > 0; off >>= 1)
        s += __shfl_xor_sync(0xFFFFFFFFu, s, off);
    int lane = i & 31, wid = i >> 5;
    if (lane == 0) warp_sums[wid] = s;
    __syncthreads();
    if (wid == 0) {
        float t = warp_sums[lane];
        #pragma unroll
        for (int off = 16; off > 0; off >>= 1)
            t += __shfl_xor_sync(0xFFFFFFFFu, t, off);
        if (lane == 0) g_sg_total = t;
    }
}

// ---------------------------------------------------------------------------
// Kernel B: transpose x [B, IN] -> xT [IN, B]  (coalesced both sides via tile)
// grid (IN/32, B/32), block (32, 32)
// ---------------------------------------------------------------------------
__global__ void transpose_kernel(const float* __restrict__ x) {
    __shared__ float tile[32][33];
    int i = blockIdx.x * 32 + threadIdx.x;
    int b = blockIdx.y * 32 + threadIdx.y;
    tile[threadIdx.y][threadIdx.x] = x[b * IN_DIM + i];
    __syncthreads();
    int i2 = blockIdx.x * 32 + threadIdx.y;
    int b2 = blockIdx.y * 32 + threadIdx.x;
    g_xT[i2 * B_DIM + b2] = tile[threadIdx.x][threadIdx.y];
}

// ---------------------------------------------------------------------------
// Main kernel: grid = OUT*2 (o, b-half), block = 256 = 32 b-lanes x 8 i-slices.
// Each thread: fixed (b, s), accumulates acc[m] over its 128-wide i slice.
// Inner math per element: u = fma(0.25*W, x, -0.25*q); acc += g * tanh(u)
// (the "+ g" constant part is folded into sg_total once, outside the loop)
// ---------------------------------------------------------------------------
__global__ void __launch_bounds__(256)
dnm_main_kernel(const float* __restrict__ W,
                const float* __restrict__ Q,
                const float* __restrict__ kptr,
                const float* __restrict__ qsptr,
                float* __restrict__ out) {
    __shared__ float ws[M_DIM * IN_DIM];   // 0.25 * W[o]
    __shared__ float qn[M_DIM * IN_DIM];   // -0.25 * q[o]
    __shared__ float red[M_DIM * 32 * 8];  // partial d reductions

    const int o    = blockIdx.x >> 1;
    const int half = blockIdx.x & 1;
    const int tid  = threadIdx.x;

    // Stage pre-scaled W, q for this o (5*1024 floats each, float4 coalesced)
    {
        const float4* W4 = reinterpret_cast<const float4*>(W + o * (M_DIM * IN_DIM));
        const float4* Q4 = reinterpret_cast<const float4*>(Q + o * (M_DIM * IN_DIM));
        float4* ws4 = reinterpret_cast<float4*>(ws);
        float4* qn4 = reinterpret_cast<float4*>(qn);
        #pragma unroll
        for (int idx = tid; idx < (M_DIM * IN_DIM) / 4; idx += 256) {
            float4 w = W4[idx];
            float4 q = Q4[idx];
            ws4[idx] = make_float4(0.25f * w.x, 0.25f * w.y, 0.25f * w.z, 0.25f * w.w);
            qn4[idx] = make_float4(-0.25f * q.x, -0.25f * q.y, -0.25f * q.z, -0.25f * q.w);
        }
    }
    __syncthreads();

    const int lane = tid & 31;
    const int s    = tid >> 5;                // i-slice 0..7
    const int b    = lane + (half << 5);      // global batch index

    float acc[M_DIM];
    #pragma unroll
    for (int m = 0; m < M_DIM; ++m) acc[m] = 0.0f;

    const float* xcol = g_xT + b;

    // 32 steps of 4 over this thread's 128-wide i slice
    for (int j = 0; j < 32; ++j) {
        const int i = (s << 7) + (j << 2);

        float4 g4 = *reinterpret_cast<const float4*>(g_half + i);  // uniform LDG
        float x0 = xcol[(i + 0) * B_DIM];   // coalesced across lanes (b)
        float x1 = xcol[(i + 1) * B_DIM];
        float x2 = xcol[(i + 2) * B_DIM];
        float x3 = xcol[(i + 3) * B_DIM];

        #pragma unroll
        for (int m = 0; m < M_DIM; ++m) {
            const float4 w4 = *reinterpret_cast<const float4*>(ws + m * IN_DIM + i); // broadcast LDS
            const float4 q4 = *reinterpret_cast<const float4*>(qn + m * IN_DIM + i);
            float a = acc[m];
            a = fmaf(g4.x, tanh_apx(fmaf(w4.x, x0, q4.x)), a);
            a = fmaf(g4.y, tanh_apx(fmaf(w4.y, x1, q4.y)), a);
            a = fmaf(g4.z, tanh_apx(fmaf(w4.z, x2, q4.z)), a);
            a = fmaf(g4.w, tanh_apx(fmaf(w4.w, x3, q4.w)), a);
            acc[m] = a;
        }
    }

    // Cross-slice reduction: 8 partials per (b, m)
    #pragma unroll
    for (int m = 0; m < M_DIM; ++m)
        red[(m * 32 + lane) * 8 + s] = acc[m];
    __syncthreads();

    if (tid < 32) {
        const float sgt = g_sg_total;
        float y = 0.0f;
        #pragma unroll
        for (int m = 0; m < M_DIM; ++m) {
            float d = sgt;
            #pragma unroll
            for (int ss = 0; ss < 8; ++ss)
                d += red[(m * 32 + tid) * 8 + ss];
            // outer sigmoid(d) = 0.5 + 0.5*tanh(0.5*d)
            y += 0.5f + 0.5f * tanh_apx(0.5f * d);
        }
        const int bb = tid + (half << 5);
        out[bb * OUT_DIM + o] = kptr[0] * (y - qsptr[0]);
    }
}

// ---------------------------------------------------------------------------
// Launch
// Inputs (metadata order): x, Synapse_W, Synapse_q, Dendritic_W2, k, qs
// Output: float [B, OUT]
// ---------------------------------------------------------------------------
extern "C" void kernel_launch(void* const* d_in, const int* in_sizes, int n_in,
                              void* d_out, int out_size) {
    const float* x  = (const float*)d_in[0];
    const float* W  = (const float*)d_in[1];
    const float* Q  = (const float*)d_in[2];
    const float* D2 = (const float*)d_in[3];
    const float* k  = (const float*)d_in[4];
    const float* qs = (const float*)d_in[5];
    float* out = (float*)d_out;

    prep_kernel<<<1, IN_DIM>>>(D2);
    transpose_kernel<<<dim3(IN_DIM / 32, B_DIM / 32), dim3(32, 32)>>>(x);
    dnm_main_kernel<<<OUT_DIM * 2, 256>>>(W, Q, k, qs, out);
}